// round 17
// baseline (speedup 1.0000x reference)
#include <cuda_runtime.h>
#include <cuda_fp16.h>
#include <cstdint>

#define CDIM 256
#define MAX_ROWS 32768
#define MAX_KCB  4096

#define M_TILE 128
#define N_CHUNK 128
#define KT 64                 // halfs per k-window (= 128 B per row)
#define ROWB 128
#define THREADS 256
#define MARGIN 0.15f
#define FB_R 16
#define PAD_F 260             // padded row stride (floats): 16B-aligned, conflict-free

// smem (occ 2): 3 stages of (A 16KB + B 16KB), then reduction arrays
#define ASTG    (M_TILE * ROWB)             // 16384
#define STG     (2 * ASTG)                  // 32768
#define NBUF    3
#define SM_RED  (NBUF * STG)                // 98304
#define SMEM_TOTAL (SM_RED + 128 * 8 + 128 * 4)   // 99840 (x2 CTA <= 227KB)

// fallback dynamic smem: xs[FB_R][PAD_F] + cbs[32][PAD_F] + rowids[FB_R]
#define FB_SMEM ((FB_R + 32) * PAD_F * 4 + FB_R * 4)   // 49984 B

// ---------------- device globals ----------------
__device__ int    g_idx[MAX_ROWS];
__device__ int    g_list[MAX_ROWS];
__device__ int    g_cnt;
__device__ float  g_e2[MAX_KCB];
__device__ float  g_partial[MAX_ROWS];
__device__ float  g_x2s[MAX_ROWS];
__device__ __half g_x0[MAX_ROWS * CDIM];
__device__ __half g_c0[MAX_KCB * CDIM];

// ---------------- PTX helpers ----------------
__device__ __forceinline__ uint32_t smem_u32(const void* p) {
    uint32_t a;
    asm("{ .reg .u64 t; cvta.to.shared.u64 t, %1; cvt.u32.u64 %0, t; }"
        : "=r"(a) : "l"(p));
    return a;
}

#define CP_ASYNC16(dst, src) \
    asm volatile("cp.async.cg.shared.global [%0], [%1], 16;" :: "r"(dst), "l"(src))
#define CP_COMMIT()  asm volatile("cp.async.commit_group;")
#define CP_WAIT1()   asm volatile("cp.async.wait_group 1;")
#define CP_WAIT0()   asm volatile("cp.async.wait_group 0;")

#define LDSM_X4(r0, r1, r2, r3, addr)                                          \
    asm volatile("ldmatrix.sync.aligned.m8n8.x4.shared.b16 {%0,%1,%2,%3}, [%4];" \
        : "=r"(r0), "=r"(r1), "=r"(r2), "=r"(r3) : "r"(addr))

#define MMA16816(d, a0, a1, a2, a3, b0, b1)                                    \
    asm volatile("mma.sync.aligned.m16n8k16.row.col.f32.f16.f16.f32 "          \
        "{%0,%1,%2,%3},{%4,%5,%6,%7},{%8,%9},{%0,%1,%2,%3};"                   \
        : "+f"((d)[0]), "+f"((d)[1]), "+f"((d)[2]), "+f"((d)[3])               \
        : "r"(a0), "r"(a1), "r"(a2), "r"(a3), "r"(b0), "r"(b1))

__device__ __forceinline__ uint32_t fkey(float f) {
    uint32_t u = __float_as_uint(f);
    return u ^ ((u & 0x80000000u) ? 0xFFFFFFFFu : 0x80000000u);
}
__device__ __forceinline__ float unfkey(uint32_t k) {
    uint32_t u = (k & 0x80000000u) ? (k ^ 0x80000000u) : ~k;
    return __uint_as_float(u);
}

// ---------------------------------------------------------------------------
// fused convert: fp32 -> fp16 row + ||row||^2. One warp per row.
// ---------------------------------------------------------------------------
__global__ void convert_kernel(const float* __restrict__ src,
                               __half* __restrict__ dsth,
                               float* __restrict__ dstn, int rows) {
    int row = blockIdx.x * 8 + (threadIdx.x >> 5);
    int lane = threadIdx.x & 31;
    if (blockIdx.x == 0 && threadIdx.x == 0) g_cnt = 0;
    if (row >= rows) return;
    const float4* p = (const float4*)(src + (size_t)row * CDIM);
    float s = 0.f;
    #pragma unroll
    for (int i = 0; i < 2; i++) {
        int c4 = lane + 32 * i;
        float4 v = p[c4];
        s += v.x * v.x + v.y * v.y + v.z * v.z + v.w * v.w;
        __half2 lo = __halves2half2(__float2half_rn(v.x), __float2half_rn(v.y));
        __half2 hi = __halves2half2(__float2half_rn(v.z), __float2half_rn(v.w));
        uint2 pk = make_uint2(*(uint32_t*)&lo, *(uint32_t*)&hi);
        *(uint2*)(dsth + (size_t)row * CDIM + c4 * 4) = pk;
    }
    #pragma unroll
    for (int o = 16; o; o >>= 1) s += __shfl_xor_sync(0xffffffffu, s, o);
    if (lane == 0) dstn[row] = s;
}

// ---------------------------------------------------------------------------
// Phase 1: approx GEMM (h0*c0, fp32 acc) + top-2 argmin + margin flag.
// 256 threads = 8 warps as 2(m) x 4(n), warp tile 64x32, N_CHUNK=128.
// Streaming A+B stages, NBUF=3, occ 2, one wave (grid 256 <= 296 slots).
// ---------------------------------------------------------------------------
__global__ void __launch_bounds__(THREADS, 2)
mma_argmin_kernel(int kcb) {
    extern __shared__ char smem[];
    const uint32_t sb = smem_u32(smem);
    const int tid = threadIdx.x;
    const int wid = tid >> 5, lane = tid & 31;
    const int warp_m = wid & 1, warp_n = wid >> 1;     // 2 x 4
    const int rowBase = blockIdx.x * M_TILE;
    const int nChunks = kcb / N_CHUNK;            // 8
    const int S = nChunks * 4;                    // 32 stages

    // ---- stage loader: A(rowBase, kc) + B(chunk c, kc) ----
    auto load_stage = [&](int s) {
        const int c = s >> 2, kc = s & 3;
        const char* asrc = (const char*)(g_x0 + (size_t)rowBase * CDIM + kc * KT);
        const char* bsrc = (const char*)(g_c0 + (size_t)(c * N_CHUNK) * CDIM + kc * KT);
        const uint32_t ab = sb + (s % NBUF) * STG;
        const uint32_t bb = ab + ASTG;
        #pragma unroll
        for (int i = 0; i < 4; i++) {              // 1024 units each
            int u = tid + THREADS * i;
            int r = u >> 3, q = u & 7;
            uint32_t so = r * ROWB + ((q ^ (r & 7)) * 16);
            CP_ASYNC16(ab + so, asrc + (size_t)r * (CDIM * 2) + q * 16);
            CP_ASYNC16(bb + so, bsrc + (size_t)r * (CDIM * 2) + q * 16);
        }
        CP_COMMIT();
    };

    load_stage(0);
    load_stage(1);

    // red arrays
    unsigned long long* red1 = (unsigned long long*)(smem + SM_RED);
    unsigned int* red2 = (unsigned int*)(smem + SM_RED + 128 * 8);
    for (int i = tid; i < M_TILE; i += THREADS) {
        red1[i] = 0xFFFFFFFFFFFFFFFFull;
        red2[i] = 0xFFFFFFFFu;
    }

    // ldmatrix address components
    const int lrow = lane & 15;
    const int hi   = lane >> 4;
    const int xorl = lrow & 7;
    uint32_t arow[4], brow[2];
    #pragma unroll
    for (int mt = 0; mt < 4; mt++)
        arow[mt] = (warp_m * 64 + mt * 16 + lrow) * ROWB;
    #pragma unroll
    for (int p = 0; p < 2; p++)
        brow[p] = (warp_n * 32 + p * 16 + lrow) * ROWB;

    float acc[4][4][4];
    #pragma unroll
    for (int mt = 0; mt < 4; mt++)
        #pragma unroll
        for (int nt = 0; nt < 4; nt++)
            #pragma unroll
            for (int e = 0; e < 4; e++) acc[mt][nt][e] = 0.f;

    float best[8], best2[8];
    int   bidx[8];
    #pragma unroll
    for (int i = 0; i < 8; i++) { best[i] = 3.4e38f; best2[i] = 3.4e38f; bidx[i] = 0; }

    for (int s = 0; s < S; s++) {
        if (s == S - 1) CP_WAIT0(); else CP_WAIT1();
        __syncthreads();
        if (s + 2 < S) load_stage(s + 2);

        const uint32_t ab = sb + (s % NBUF) * STG;
        const uint32_t bb = ab + ASTG;

        #pragma unroll
        for (int ks = 0; ks < 4; ks++) {
            const uint32_t koff = ((uint32_t)((ks * 2 + hi) ^ xorl)) * 16;
            uint32_t ar[4][4];
            uint32_t br[4][2];
            #pragma unroll
            for (int p = 0; p < 2; p++) {
                uint32_t r0, r1, r2, r3;
                LDSM_X4(r0, r1, r2, r3, bb + brow[p] + koff);
                br[2 * p][0] = r0; br[2 * p][1] = r2;
                br[2 * p + 1][0] = r1; br[2 * p + 1][1] = r3;
            }
            #pragma unroll
            for (int mt = 0; mt < 4; mt++)
                LDSM_X4(ar[mt][0], ar[mt][1], ar[mt][2], ar[mt][3],
                        ab + arow[mt] + koff);
            #pragma unroll
            for (int mt = 0; mt < 4; mt++)
                #pragma unroll
                for (int nt = 0; nt < 4; nt++)
                    MMA16816(acc[mt][nt],
                             ar[mt][0], ar[mt][1], ar[mt][2], ar[mt][3],
                             br[nt][0], br[nt][1]);
        }

        // ---- chunk epilogue: score + top-2 update ----
        if ((s & 3) == 3) {
            const int c = s >> 2;
            const int colBase = c * N_CHUNK + warp_n * 32 + (lane & 3) * 2;
            #pragma unroll
            for (int nt = 0; nt < 4; nt++) {
                const int n0 = colBase + nt * 8;
                float2 e2v = *(const float2*)&g_e2[n0];
                #pragma unroll
                for (int mt = 0; mt < 4; mt++) {
                    float sc[4];
                    sc[0] = e2v.x - 2.f * acc[mt][nt][0];
                    sc[1] = e2v.y - 2.f * acc[mt][nt][1];
                    sc[2] = e2v.x - 2.f * acc[mt][nt][2];
                    sc[3] = e2v.y - 2.f * acc[mt][nt][3];
                    #pragma unroll
                    for (int e = 0; e < 4; e++) {
                        int slot = mt * 2 + (e >> 1);
                        int col  = n0 + (e & 1);
                        if (sc[e] < best[slot]) {
                            best2[slot] = best[slot];
                            best[slot] = sc[e];
                            bidx[slot] = col;
                        } else if (sc[e] < best2[slot]) {
                            best2[slot] = sc[e];
                        }
                        acc[mt][nt][e] = 0.f;
                    }
                }
            }
        }
    }

    // ---- cross-thread top-2 merge ----
    __syncthreads();
    #pragma unroll
    for (int slot = 0; slot < 8; slot++) {
        int mt = slot >> 1, h = slot & 1;
        int rl = warp_m * 64 + mt * 16 + (lane >> 2) + h * 8;
        unsigned long long pk =
            ((unsigned long long)fkey(best[slot]) << 32) |
            (unsigned long long)(uint32_t)bidx[slot];
        atomicMin(&red1[rl], pk);
    }
    __syncthreads();
    #pragma unroll
    for (int slot = 0; slot < 8; slot++) {
        int mt = slot >> 1, h = slot & 1;
        int rl = warp_m * 64 + mt * 16 + (lane >> 2) + h * 8;
        int widx = (int)(red1[rl] & 0xFFFFFFFFu);
        float cand = (bidx[slot] == widx) ? best2[slot] : best[slot];
        atomicMin(&red2[rl], fkey(cand));
    }
    __syncthreads();
    if (tid < M_TILE) {
        unsigned long long pk = red1[tid];
        float b1 = unfkey((uint32_t)(pk >> 32));
        float b2 = unfkey(red2[tid]);
        int row = rowBase + tid;
        g_idx[row] = (int)(pk & 0xFFFFFFFFu);
        g_partial[row] = g_x2s[row] + b1;
        if (b2 - b1 < MARGIN) {
            int p = atomicAdd(&g_cnt, 1);
            g_list[p] = row;
        }
    }
}

// ---------------------------------------------------------------------------
// Phase 2: exact fp32 re-scoring of flagged rows. FB_R rows per block.
// Codebook tiled through DYNAMIC smem (coalesced loads); lane = codeword;
// warp w owns rows {2w, 2w+1}; warp-shuffle argmin (no atomics).
// ---------------------------------------------------------------------------
__global__ void __launch_bounds__(256, 2)
exact_fallback_kernel(const float* __restrict__ x,
                      const float* __restrict__ cb, int kcb) {
    int base = blockIdx.x * FB_R;
    int cnt = g_cnt;
    if (base >= cnt) return;
    int nr = min(FB_R, cnt - base);

    extern __shared__ float fsm[];
    float* xs  = fsm;                          // [FB_R][PAD_F]
    float* cbs = fsm + FB_R * PAD_F;           // [32][PAD_F]
    int* rowids = (int*)(fsm + (FB_R + 32) * PAD_F);   // [FB_R]

    int t = threadIdx.x;   // 256
    int lane = t & 31, w = t >> 5;    // warp w -> rows 2w, 2w+1; lane -> k in tile

    if (t < FB_R) rowids[t] = (t < nr) ? g_list[base + t] : -1;
    __syncthreads();
    for (int i = t; i < nr * (CDIM / 4); i += 256) {
        int r = i >> 6, c4 = i & 63;
        *(float4*)&xs[r * PAD_F + c4 * 4] =
            ((const float4*)(x + (size_t)rowids[r] * CDIM))[c4];
    }

    const int r0 = 2 * w, r1 = 2 * w + 1;
    float bv0 = 3.4e38f, bv1 = 3.4e38f;
    int   bk0 = 0, bk1 = 0;

    for (int kt = 0; kt < kcb; kt += 32) {
        __syncthreads();
        // coalesced codebook tile load: 32 rows x 64 float4
        for (int i = t; i < 32 * 64; i += 256) {
            int r = i >> 6, c4 = i & 63;
            *(float4*)&cbs[r * PAD_F + c4 * 4] =
                ((const float4*)(cb + (size_t)(kt + r) * CDIM))[c4];
        }
        __syncthreads();

        float a0 = 0.f, a1 = 0.f;
        #pragma unroll 8
        for (int d = 0; d < 64; d++) {
            float4 c = *(const float4*)&cbs[lane * PAD_F + d * 4];
            float4 v0 = *(const float4*)&xs[r0 * PAD_F + d * 4];
            float4 v1 = *(const float4*)&xs[r1 * PAD_F + d * 4];
            a0 += c.x * v0.x + c.y * v0.y + c.z * v0.z + c.w * v0.w;
            a1 += c.x * v1.x + c.y * v1.y + c.z * v1.z + c.w * v1.w;
        }
        int k = kt + lane;
        float e2k = g_e2[k];
        float s0 = e2k - 2.f * a0;
        float s1 = e2k - 2.f * a1;
        if (s0 < bv0) { bv0 = s0; bk0 = k; }
        if (s1 < bv1) { bv1 = s1; bk1 = k; }
    }

    // warp-level argmin over lanes for the warp's two rows
    unsigned long long p0 =
        ((unsigned long long)fkey(bv0) << 32) | (unsigned long long)(uint32_t)bk0;
    unsigned long long p1 =
        ((unsigned long long)fkey(bv1) << 32) | (unsigned long long)(uint32_t)bk1;
    #pragma unroll
    for (int o = 16; o; o >>= 1) {
        unsigned long long q0 = __shfl_xor_sync(0xffffffffu, p0, o);
        unsigned long long q1 = __shfl_xor_sync(0xffffffffu, p1, o);
        if (q0 < p0) p0 = q0;
        if (q1 < p1) p1 = q1;
    }
    if (lane == 0) {
        if (r0 < nr) {
            int row = rowids[r0];
            g_idx[row] = (int)(p0 & 0xFFFFFFFFu);
            g_partial[row] = g_x2s[row] + unfkey((uint32_t)(p0 >> 32));
        }
        if (r1 < nr) {
            int row = rowids[r1];
            g_idx[row] = (int)(p1 & 0xFFFFFFFFu);
            g_partial[row] = g_x2s[row] + unfkey((uint32_t)(p1 >> 32));
        }
    }
}

// ---------------------------------------------------------------------------
__global__ void gather_kernel(const float* __restrict__ cbk,
                              float* __restrict__ outq,
                              float* __restrict__ outidx) {
    int row = blockIdx.x;
    int t = threadIdx.x;   // 64
    int idx = g_idx[row];
    float4 q = *(const float4*)(cbk + (size_t)idx * CDIM + t * 4);
    *(float4*)(outq + (size_t)row * CDIM + t * 4) = q;
    if (t == 0 && outidx) outidx[row] = (float)idx;
}

__global__ void finalize_kernel(float* __restrict__ outloss, int rows, int qn) {
    __shared__ double sh[1024];
    const float4* p4 = (const float4*)g_partial;
    double s = 0.0;
    for (int i = threadIdx.x; i < rows / 4; i += 1024) {
        float4 v = p4[i];
        s += (double)v.x + (double)v.y + (double)v.z + (double)v.w;
    }
    sh[threadIdx.x] = s;
    __syncthreads();
    for (int st = 512; st; st >>= 1) {
        if (threadIdx.x < st) sh[threadIdx.x] += sh[threadIdx.x + st];
        __syncthreads();
    }
    if (threadIdx.x == 0)
        *outloss = (float)(1.25 * sh[0] / (double)qn);
}

// ---------------------------------------------------------------------------
extern "C" void kernel_launch(void* const* d_in, const int* in_sizes, int n_in,
                              void* d_out, int out_size) {
    const float* x  = (const float*)d_in[0];
    const float* cb = (const float*)d_in[1];
    float* out = (float*)d_out;

    const int qn   = in_sizes[0];          // 8*4096*256
    const int kcb  = in_sizes[1] / CDIM;   // 1024
    const int rows = qn / CDIM;            // 32768

    __half *px0, *pc0;
    float *pe2, *px2;
    cudaGetSymbolAddress((void**)&px0, g_x0);
    cudaGetSymbolAddress((void**)&pc0, g_c0);
    cudaGetSymbolAddress((void**)&pe2, g_e2);
    cudaGetSymbolAddress((void**)&px2, g_x2s);

    convert_kernel<<<(rows + 7) / 8, 256>>>(x, px0, px2, rows);
    convert_kernel<<<(kcb + 7) / 8, 256>>>(cb, pc0, pe2, kcb);

    cudaFuncSetAttribute(mma_argmin_kernel,
                         cudaFuncAttributeMaxDynamicSharedMemorySize, SMEM_TOTAL);
    mma_argmin_kernel<<<rows / M_TILE, THREADS, SMEM_TOTAL>>>(kcb);

    cudaFuncSetAttribute(exact_fallback_kernel,
                         cudaFuncAttributeMaxDynamicSharedMemorySize, FB_SMEM);
    exact_fallback_kernel<<<rows / FB_R, 256, FB_SMEM>>>(x, cb, kcb);

    bool has_loss = out_size >= qn + 1;
    bool has_idx  = out_size >= qn + 1 + rows;
    float* outidx = has_idx ? (out + qn + 1) : nullptr;

    gather_kernel<<<rows, 64>>>(cb, out, outidx);
    if (has_loss)
        finalize_kernel<<<1, 1024>>>(out + qn, rows, qn);
}